// round 1
// baseline (speedup 1.0000x reference)
#include <cuda_runtime.h>
#include <math.h>

// Problem dims (fixed by the dataset)
#define B    32
#define NIN  2312
#define NHID 512
#define NOUT 10
#define TT   350
#define NCOL (B * TT)   // 11200 (b, t) columns
#define MAXN 256        // max active inputs per column (mean ~69, binomial tail << 256)

// ---------------- device scratch (static, no allocation) ----------------
__device__ __align__(256) float g_W1T[NIN * NHID];    // 4.7 MB, transposed weights
__device__            int       g_cnt[NCOL];
__device__            int       g_idx[NCOL * MAXN];   // 11.5 MB active-input lists
__device__ __align__(256) float g_z1[NCOL * NHID];    // 22.9 MB, layout [(b*T+t)*NHID + o]
__device__ __align__(256) float g_s1[NCOL * NHID];    // 22.9 MB, same layout
__device__ __align__(256) float g_z2[NCOL * NOUT];    // 448 KB, layout [(b*T+t)*NOUT + o]

// ---------------- 1) W1 (NHID x NIN) -> W1T (NIN x NHID) ----------------
__global__ void k_transpose(const float* __restrict__ W1) {
    __shared__ float tile[32][33];
    int o0 = blockIdx.x * 32;   // output-neuron tile (512/32 = 16, exact)
    int i0 = blockIdx.y * 32;   // input-neuron tile  (ceil(2312/32) = 73)
    int tx = threadIdx.x, ty = threadIdx.y;  // (32, 8)
#pragma unroll
    for (int k = 0; k < 4; k++) {
        int o = o0 + ty + 8 * k;
        int i = i0 + tx;
        tile[ty + 8 * k][tx] = (i < NIN) ? W1[(size_t)o * NIN + i] : 0.f;
    }
    __syncthreads();
#pragma unroll
    for (int k = 0; k < 4; k++) {
        int i = i0 + ty + 8 * k;
        int o = o0 + tx;
        if (i < NIN) g_W1T[(size_t)i * NHID + o] = tile[tx][ty + 8 * k];
    }
}

// ---------------- 2) pack input events: per (b,t) list of active i ----------------
// Input layout (B, NIN, T): lane = t gives coalesced 128B reads along t.
__global__ void k_pack(const float* __restrict__ x) {
    int w = blockIdx.x * (blockDim.x >> 5) + (threadIdx.x >> 5);
    int lane = threadIdx.x & 31;
    if (w >= B * 11) return;          // 11 t-warps of 32 cover T=350
    int b = w / 11, tw = w % 11;
    int t = tw * 32 + lane;
    if (t >= TT) return;
    const float* px = x + (size_t)b * NIN * TT + t;
    int col = b * TT + t;
    int cnt = 0;
    for (int i = 0; i < NIN; i++) {
        float v = px[(size_t)i * TT];
        if (v != 0.f) {
            if (cnt < MAXN) g_idx[col * MAXN + cnt] = i;
            cnt++;
        }
    }
    g_cnt[col] = (cnt < MAXN) ? cnt : MAXN;
}

// ---------------- 3) sparse gather: z1[col, :] = sum over active i of W1T[i, :] ----------------
// Spike magnitudes are exactly 1.0 (1/Ts with Ts=1), so the matmul is a pure column gather-sum.
__global__ void __launch_bounds__(128) k_gather() {
    int col = blockIdx.x;
    __shared__ int sh[MAXN];
    int cnt = g_cnt[col];
    for (int j = threadIdx.x; j < cnt; j += 128) sh[j] = g_idx[col * MAXN + j];
    __syncthreads();
    int tid = threadIdx.x;
    const float4* WT = (const float4*)g_W1T;   // row = 128 float4s
    float4 a0 = {0.f, 0.f, 0.f, 0.f}, a1 = a0, a2 = a0, a3 = a0;
    int j = 0;
    for (; j + 4 <= cnt; j += 4) {
        float4 w0 = WT[sh[j    ] * 128 + tid];
        float4 w1 = WT[sh[j + 1] * 128 + tid];
        float4 w2 = WT[sh[j + 2] * 128 + tid];
        float4 w3 = WT[sh[j + 3] * 128 + tid];
        a0.x += w0.x; a0.y += w0.y; a0.z += w0.z; a0.w += w0.w;
        a1.x += w1.x; a1.y += w1.y; a1.z += w1.z; a1.w += w1.w;
        a2.x += w2.x; a2.y += w2.y; a2.z += w2.z; a2.w += w2.w;
        a3.x += w3.x; a3.y += w3.y; a3.z += w3.z; a3.w += w3.w;
    }
    for (; j < cnt; j++) {
        float4 w = WT[sh[j] * 128 + tid];
        a0.x += w.x; a0.y += w.y; a0.z += w.z; a0.w += w.w;
    }
    float4 a;
    a.x = (a0.x + a1.x) + (a2.x + a3.x);
    a.y = (a0.y + a1.y) + (a2.y + a3.y);
    a.z = (a0.z + a1.z) + (a2.z + a3.z);
    a.w = (a0.w + a1.w) + (a2.w + a3.w);
    ((float4*)g_z1)[(size_t)col * 128 + tid] = a;
}

// ---------------- 4) fused psp (truncated alpha conv, exact via recurrence+delayed-tail) + spike ----------------
// psp kernel k[j] = (e/10) * j * d^j, d = exp(-0.1), truncated to j in [0, 76].
// psp[t] = (e/10) * ( y[t] - d^77 * ( y2[t] + 77*x2[t] ) )
//   (x, y)  fed by z[t];  (x2, y2) fed by z[t-77]  (the truncation-tail correction).
// spike:   yr = DR*(yr+xr); u = psp + CR*yr; spk = (u >= 10); xr = DR*xr + spk.
__device__ __forceinline__ void rec_core(const float* __restrict__ zin,
                                         float* __restrict__ sout,
                                         int C, int outMode, int gid) {
    const float d    = (float)exp(-0.1);
    const float D77  = (float)exp(-7.7);
    const float coef = (float)(exp(1.0) / 10.0);
    const float DR   = (float)exp(-1.0);
    const float CR   = (float)(-20.0 * exp(1.0));   // -SCALE_REF*THETA*e*TS/TAU_REF

    int b = gid / C, o = gid % C;
    const float* p = zin + (size_t)b * TT * C + o;   // element t at p[t*C]

    float x = 0.f, y = 0.f, x2 = 0.f, y2 = 0.f, xr = 0.f, yr = 0.f;
    float cur[8], curd[8];
#pragma unroll
    for (int k = 0; k < 8; k++) { cur[k] = p[(size_t)k * C]; curd[k] = 0.f; }  // t<8: t-77 < 0

    for (int tb = 0; tb < 352; tb += 8) {
        float nxt[8], nxtd[8];
#pragma unroll
        for (int k = 0; k < 8; k++) {           // prefetch next block to hide L2 latency
            int t2 = tb + 8 + k;
            nxt[k] = (t2 < TT) ? p[(size_t)t2 * C] : 0.f;
            int td = t2 - 77;
            nxtd[k] = (td >= 0 && td < TT) ? p[(size_t)td * C] : 0.f;
        }
#pragma unroll
        for (int k = 0; k < 8; k++) {
            int t = tb + k;
            if (t < TT) {
                y  = d * (y  + x );  x  = d * x  + cur[k];
                y2 = d * (y2 + x2);  x2 = d * x2 + curd[k];
                float pp = coef * (y - D77 * (y2 + 77.f * x2));
                yr = DR * (yr + xr);
                float u = pp + CR * yr;
                float spk = (u >= 10.f) ? 1.f : 0.f;
                xr = DR * xr + spk;
                size_t oidx = outMode ? ((size_t)(b * C + o) * TT + t)
                                      : ((size_t)(b * TT + t) * C + o);
                sout[oidx] = spk;   // spike magnitude spk/Ts with Ts=1
            }
        }
#pragma unroll
        for (int k = 0; k < 8; k++) { cur[k] = nxt[k]; curd[k] = nxtd[k]; }
    }
}

__global__ void __launch_bounds__(128) k_rec1() {
    int gid = blockIdx.x * 128 + threadIdx.x;
    if (gid >= B * NHID) return;
    rec_core(g_z1, g_s1, NHID, 0, gid);
}

__global__ void __launch_bounds__(128) k_rec2(float* __restrict__ out) {
    int gid = blockIdx.x * 128 + threadIdx.x;
    if (gid >= B * NOUT) return;
    rec_core(g_z2, out, NOUT, 1, gid);
}

// ---------------- 5) layer-2 GEMV: z2[col, w] = W2[w, :] . s1[col, :] ----------------
__global__ void __launch_bounds__(320) k_gemv2(const float* __restrict__ W2) {
    int col = blockIdx.x;
    int w = threadIdx.x >> 5, lane = threadIdx.x & 31;
    const float* s  = g_s1 + (size_t)col * NHID;
    const float* wr = W2 + (size_t)w * NHID;
    float sum = 0.f;
#pragma unroll
    for (int h = lane; h < NHID; h += 32) sum += wr[h] * s[h];
#pragma unroll
    for (int off = 16; off; off >>= 1) sum += __shfl_xor_sync(0xffffffffu, sum, off);
    if (lane == 0) g_z2[(size_t)col * NOUT + w] = sum;
}

// ---------------- launch ----------------
extern "C" void kernel_launch(void* const* d_in, const int* in_sizes, int n_in,
                              void* d_out, int out_size) {
    const float* x  = (const float*)d_in[0];   // spikeInput (32, 2312, 350)
    const float* W1 = (const float*)d_in[1];   // (512, 2312)
    const float* W2 = (const float*)d_in[2];   // (10, 512)
    float* out = (float*)d_out;                // (32, 10, 350)

    k_transpose<<<dim3(NHID / 32, (NIN + 31) / 32), dim3(32, 8)>>>(W1);
    k_pack<<<(B * 11 + 7) / 8, 256>>>(x);
    k_gather<<<NCOL, 128>>>();
    k_rec1<<<(B * NHID) / 128, 128>>>();
    k_gemv2<<<NCOL, 320>>>(W2);
    k_rec2<<<(B * NOUT + 127) / 128, 128>>>(out);
}

// round 2
// speedup vs baseline: 1.9833x; 1.9833x over previous
#include <cuda_runtime.h>
#include <cuda_bf16.h>
#include <math.h>

// Problem dims (fixed by the dataset)
#define B    32
#define NIN  2312
#define NHID 512
#define NOUT 10
#define TT   350
#define NCOL (B * TT)   // 11200 (b, t) columns
#define NCHK 8          // input chunks for parallel pack
#define CE   289        // NIN / NCHK (exact: 2312/8)
#define SUBN 48         // max events per (col, chunk); mean 8.7, 48 is >10 sigma
#define MAXTOT (NCHK * SUBN)   // 384

// ---------------- device scratch (static, no allocation) ----------------
__device__ __align__(256) __nv_bfloat16 g_W1Tb[NIN * NHID];  // 2.37 MB transposed bf16 weights
__device__            int  g_cntc[NCOL * NCHK];
__device__            int  g_idx[NCOL * MAXTOT];             // per-(col,chunk) sub-lists
__device__ __align__(256) float g_z1[NCOL * NHID];           // [(b*T+t)*NHID + o]
__device__ __align__(256) float g_s1[NCOL * NHID];
__device__ __align__(256) float g_z2[NCOL * NOUT];

// ---------------- 1) W1 (NHID x NIN) -> W1T bf16 (NIN x NHID) ----------------
__global__ void k_transpose(const float* __restrict__ W1) {
    __shared__ float tile[32][33];
    int o0 = blockIdx.x * 32;
    int i0 = blockIdx.y * 32;
    int tx = threadIdx.x, ty = threadIdx.y;  // (32, 8)
#pragma unroll
    for (int k = 0; k < 4; k++) {
        int o = o0 + ty + 8 * k;
        int i = i0 + tx;
        tile[ty + 8 * k][tx] = (i < NIN) ? W1[(size_t)o * NIN + i] : 0.f;
    }
    __syncthreads();
#pragma unroll
    for (int k = 0; k < 4; k++) {
        int i = i0 + ty + 8 * k;
        int o = o0 + tx;
        if (i < NIN) g_W1Tb[(size_t)i * NHID + o] = __float2bfloat16(tile[tx][ty + 8 * k]);
    }
}

// ---------------- 2) pack input events (parallel over 8 input chunks) ----------------
// Input layout (B, NIN, T). lane = t gives coalesced 128B reads along t.
// Each warp owns (32 t-values) x (one chunk of 289 inputs) -> per-(col,chunk) sub-list.
__global__ void __launch_bounds__(256) k_pack(const float* __restrict__ x) {
    int b  = blockIdx.x;            // 32
    int t0 = blockIdx.y * 32;       // 11 warps of t
    int tx = threadIdx.x & 31;
    int c  = threadIdx.x >> 5;      // chunk 0..7
    int t  = t0 + tx;
    if (t >= TT) return;
    int col = b * TT + t;
    const float* px = x + (size_t)b * NIN * TT + t;
    int base = col * MAXTOT + c * SUBN;
    int n = 0;
#pragma unroll 8
    for (int k = 0; k < CE; k++) {
        int i = c * CE + k;
        if (px[(size_t)i * TT] != 0.f) {
            if (n < SUBN) g_idx[base + n] = i;
            n++;
        }
    }
    g_cntc[col * NCHK + c] = (n < SUBN) ? n : SUBN;
}

// ---------------- 3) sparse gather: z1[col, :] = sum over active i of W1T[i, :] ----------------
// Spike magnitudes are exactly 1.0 (1/Ts, Ts=1), so the matmul is a pure row gather-sum.
// Weights bf16 (L2-resident), accumulation fp32. 128 threads x 4 outputs = 512.
__global__ void __launch_bounds__(128) k_gather() {
    int col = blockIdx.x;
    __shared__ int sh[MAXTOT];
    __shared__ int offs[NCHK + 1];
    if (threadIdx.x == 0) {
        int acc = 0;
#pragma unroll
        for (int c = 0; c < NCHK; c++) { offs[c] = acc; acc += g_cntc[col * NCHK + c]; }
        offs[NCHK] = acc;
    }
    __syncthreads();
    {   // compact the 8 sub-lists into sh[0..cnt)
        int c = threadIdx.x >> 4, jj = threadIdx.x & 15;
        int o0 = offs[c], cc = offs[c + 1] - o0;
        for (int j = jj; j < cc; j += 16) sh[o0 + j] = g_idx[col * MAXTOT + c * SUBN + j];
    }
    __syncthreads();
    int cnt = offs[NCHK];
    int tid = threadIdx.x;
    const uint2* WT = (const uint2*)g_W1Tb;   // row = 128 uint2 (4 bf16 each)
    float4 a0 = {0.f,0.f,0.f,0.f}, a1 = a0, a2 = a0, a3 = a0;

#define ACC(A, U) { \
        __nv_bfloat162 p0 = *(__nv_bfloat162*)&(U).x;           \
        __nv_bfloat162 p1 = *(__nv_bfloat162*)&(U).y;           \
        float2 f0 = __bfloat1622float2(p0);                     \
        float2 f1 = __bfloat1622float2(p1);                     \
        A.x += f0.x; A.y += f0.y; A.z += f1.x; A.w += f1.y; }

    int j = 0;
    for (; j + 4 <= cnt; j += 4) {
        uint2 u0 = WT[sh[j    ] * 128 + tid];
        uint2 u1 = WT[sh[j + 1] * 128 + tid];
        uint2 u2 = WT[sh[j + 2] * 128 + tid];
        uint2 u3 = WT[sh[j + 3] * 128 + tid];
        ACC(a0, u0); ACC(a1, u1); ACC(a2, u2); ACC(a3, u3);
    }
    for (; j < cnt; j++) {
        uint2 u = WT[sh[j] * 128 + tid];
        ACC(a0, u);
    }
#undef ACC
    float4 a;
    a.x = (a0.x + a1.x) + (a2.x + a3.x);
    a.y = (a0.y + a1.y) + (a2.y + a3.y);
    a.z = (a0.z + a1.z) + (a2.z + a3.z);
    a.w = (a0.w + a1.w) + (a2.w + a3.w);
    ((float4*)g_z1)[(size_t)col * 128 + tid] = a;
}

// ---------------- 4) fused psp (exact truncated alpha kernel via recurrence+delayed tail) + spike ----------------
// k[j] = (e/10) * j * d^j, d = exp(-0.1), truncated to j in [0,76].
// psp[t] = (e/10) * ( y[t] - d^77 * ( y2[t] + 77*x2[t] ) ), (x2,y2) fed by z[t-77].
__device__ __forceinline__ void rec_core(const float* __restrict__ zin,
                                         float* __restrict__ sout,
                                         int C, int outMode, int gid) {
    const float d    = (float)exp(-0.1);
    const float D77  = (float)exp(-7.7);
    const float coef = (float)(exp(1.0) / 10.0);
    const float DR   = (float)exp(-1.0);
    const float CR   = (float)(-20.0 * exp(1.0));   // -SCALE_REF*THETA*e*TS/TAU_REF

    int b = gid / C, o = gid % C;
    const float* p = zin + (size_t)b * TT * C + o;   // element t at p[t*C]

    float x = 0.f, y = 0.f, x2 = 0.f, y2 = 0.f, xr = 0.f, yr = 0.f;
    float cur[8], curd[8];
#pragma unroll
    for (int k = 0; k < 8; k++) { cur[k] = p[(size_t)k * C]; curd[k] = 0.f; }

    for (int tb = 0; tb < 352; tb += 8) {
        float nxt[8], nxtd[8];
#pragma unroll
        for (int k = 0; k < 8; k++) {           // prefetch next block to hide latency
            int t2 = tb + 8 + k;
            nxt[k] = (t2 < TT) ? p[(size_t)t2 * C] : 0.f;
            int td = t2 - 77;
            nxtd[k] = (td >= 0 && td < TT) ? p[(size_t)td * C] : 0.f;
        }
#pragma unroll
        for (int k = 0; k < 8; k++) {
            int t = tb + k;
            if (t < TT) {
                y  = d * (y  + x );  x  = d * x  + cur[k];
                y2 = d * (y2 + x2);  x2 = d * x2 + curd[k];
                float pp = coef * (y - D77 * (y2 + 77.f * x2));
                yr = DR * (yr + xr);
                float u = pp + CR * yr;
                float spk = (u >= 10.f) ? 1.f : 0.f;
                xr = DR * xr + spk;
                size_t oidx = outMode ? ((size_t)(b * C + o) * TT + t)
                                      : ((size_t)(b * TT + t) * C + o);
                sout[oidx] = spk;   // spike magnitude spk/Ts, Ts=1
            }
        }
#pragma unroll
        for (int k = 0; k < 8; k++) { cur[k] = nxt[k]; curd[k] = nxtd[k]; }
    }
}

__global__ void __launch_bounds__(128) k_rec1() {
    int gid = blockIdx.x * 128 + threadIdx.x;
    if (gid >= B * NHID) return;
    rec_core(g_z1, g_s1, NHID, 0, gid);
}

__global__ void __launch_bounds__(128) k_rec2(float* __restrict__ out) {
    int gid = blockIdx.x * 128 + threadIdx.x;
    if (gid >= B * NOUT) return;
    rec_core(g_z2, out, NOUT, 1, gid);
}

// ---------------- 5) layer-2 GEMV ----------------
__global__ void __launch_bounds__(320) k_gemv2(const float* __restrict__ W2) {
    int col = blockIdx.x;
    int w = threadIdx.x >> 5, lane = threadIdx.x & 31;
    const float* s  = g_s1 + (size_t)col * NHID;
    const float* wr = W2 + (size_t)w * NHID;
    float sum = 0.f;
#pragma unroll
    for (int h = lane; h < NHID; h += 32) sum += wr[h] * s[h];
#pragma unroll
    for (int off = 16; off; off >>= 1) sum += __shfl_xor_sync(0xffffffffu, sum, off);
    if (lane == 0) g_z2[(size_t)col * NOUT + w] = sum;
}

// ---------------- launch ----------------
extern "C" void kernel_launch(void* const* d_in, const int* in_sizes, int n_in,
                              void* d_out, int out_size) {
    const float* x  = (const float*)d_in[0];   // spikeInput (32, 2312, 350)
    const float* W1 = (const float*)d_in[1];   // (512, 2312)
    const float* W2 = (const float*)d_in[2];   // (10, 512)
    float* out = (float*)d_out;                // (32, 10, 350)

    k_transpose<<<dim3(NHID / 32, (NIN + 31) / 32), dim3(32, 8)>>>(W1);
    k_pack<<<dim3(B, (TT + 31) / 32), 256>>>(x);
    k_gather<<<NCOL, 128>>>();
    k_rec1<<<(B * NHID) / 128, 128>>>();
    k_gemv2<<<NCOL, 320>>>(W2);
    k_rec2<<<(B * NOUT + 127) / 128, 128>>>(out);
}